// round 16
// baseline (speedup 1.0000x reference)
#include <cuda_runtime.h>
#include <cuda_bf16.h>
#include <cuda_fp16.h>
#include <math.h>
#include <stdint.h>

#define BATCH   16
#define SEQ     1024
#define DMODEL  512
#define NHEAD   8
#define DHEAD   64
#define ROWS    (BATCH * SEQ)          // 16384
#define LN_EPS  1e-5f
#define SM_SCALE 0.04419417382415922f  // 1/sqrt(512)
#define QB_SCALE (0.04419417382415922f * 1.4426950408889634f)  // fold log2(e)

// ---------------- scratch (device globals; no allocations allowed) ----------
__device__ __half g_qr[ROWS * DMODEL];          // q projection fp16 (residual)
__device__ __half g_att[ROWS * DMODEL];         // attention output fp16
__device__ __half g_t[ROWS * DMODEL];           // o1 + gelu(Wo gemm) fp16
__device__ __half g_af0[ROWS * DMODEL];         // Q fp16, later LN(o1) fp16
__device__ __half g_af1[ROWS * DMODEL];         // K fp16
__device__ __half g_wtq[DMODEL * DMODEL];
__device__ __half g_wtk[DMODEL * DMODEL];
__device__ __half g_wtv[DMODEL * DMODEL];
__device__ __half g_wto[DMODEL * DMODEL];
__device__ __half g_qh[ROWS * DMODEL];          // q * QB_SCALE, fp16
__device__ __half g_kh[ROWS * DMODEL];          // k, fp16
__device__ __half g_vt[ROWS * DMODEL];          // v transposed [b][h][d][seq], fp16

// ---------------- helpers ----------------------------------------------------
__device__ __forceinline__ uint32_t smem_u32(const void* p) {
    uint32_t a;
    asm("{ .reg .u64 t; cvta.to.shared.u64 t, %1; cvt.u32.u64 %0, t; }" : "=r"(a) : "l"(p));
    return a;
}
__device__ __forceinline__ void ldsm4(uint32_t* r, uint32_t addr) {
    asm volatile("ldmatrix.sync.aligned.m8n8.x4.shared.b16 {%0,%1,%2,%3}, [%4];"
                 : "=r"(r[0]), "=r"(r[1]), "=r"(r[2]), "=r"(r[3]) : "r"(addr));
}
__device__ __forceinline__ void cp16(uint32_t dst, const void* src) {
    asm volatile("cp.async.cg.shared.global [%0], [%1], 16;" :: "r"(dst), "l"(src) : "memory");
}
__device__ __forceinline__ void cp_commit() {
    asm volatile("cp.async.commit_group;" ::: "memory");
}
__device__ __forceinline__ uint32_t packh2(float a, float b) {
    uint32_t r;
    asm("cvt.rn.f16x2.f32 %0, %1, %2;" : "=r"(r) : "f"(b), "f"(a));
    return r;
}
// fp16 in, fp32 accum (projection GEMMs)
__device__ __forceinline__ void mma16816(float* d, const uint32_t* a, uint32_t b0, uint32_t b1) {
    asm volatile("mma.sync.aligned.m16n8k16.row.col.f32.f16.f16.f32 "
                 "{%0,%1,%2,%3}, {%4,%5,%6,%7}, {%8,%9}, {%0,%1,%2,%3};"
                 : "+f"(d[0]), "+f"(d[1]), "+f"(d[2]), "+f"(d[3])
                 : "r"(a[0]), "r"(a[1]), "r"(a[2]), "r"(a[3]), "r"(b0), "r"(b1));
}
// fp16 in, fp16 accum (attention)
__device__ __forceinline__ void mma16816h(uint32_t* d, const uint32_t* a, uint32_t b0, uint32_t b1) {
    asm volatile("mma.sync.aligned.m16n8k16.row.col.f16.f16.f16.f16 "
                 "{%0,%1}, {%2,%3,%4,%5}, {%6,%7}, {%0,%1};"
                 : "+r"(d[0]), "+r"(d[1])
                 : "r"(a[0]), "r"(a[1]), "r"(a[2]), "r"(a[3]), "r"(b0), "r"(b1));
}
__device__ __forceinline__ float gelu_exact(float x)
{
    return 0.5f * x * (1.0f + erff(x * 0.7071067811865475f));
}

// ---------------- fused prep: converts Q,K rows + 4 weight transposes --------
#define PREP_BLOCKS (2 * 8192 + 4 * 256)

__global__ __launch_bounds__(256) void prep_fused(
    const float4* __restrict__ Q4, const float4* __restrict__ K4,
    uint2* __restrict__ aq, uint2* __restrict__ ak,
    const float* __restrict__ Wq, const float* __restrict__ Wk,
    const float* __restrict__ Wv, const float* __restrict__ Wo,
    __half* __restrict__ wtq, __half* __restrict__ wtk,
    __half* __restrict__ wtv, __half* __restrict__ wto)
{
    const int bid = blockIdx.x;
    const int tid = threadIdx.x;
    if (bid < 16384) {
        const float4* in = (bid < 8192) ? Q4 : K4;
        uint2* out = (bid < 8192) ? aq : ak;
        const size_t i = (size_t)(bid & 8191) * 256 + tid;
        float4 v = in[i];
        uint2 o;
        o.x = packh2(v.x, v.y);
        o.y = packh2(v.z, v.w);
        out[i] = o;
    } else {
        __shared__ float t[32][33];
        const int r = bid - 16384;
        const int w = r >> 8, tile = r & 255;
        const float* W = (w == 0) ? Wq : (w == 1) ? Wk : (w == 2) ? Wv : Wo;
        __half* Wt = (w == 0) ? wtq : (w == 1) ? wtk : (w == 2) ? wtv : wto;
        const int nt = (tile & 15) * 32, kt = (tile >> 4) * 32;
        const int tx = tid & 31, ty = tid >> 5;
#pragma unroll
        for (int i = 0; i < 4; i++) {
            const int k = ty + i * 8;
            t[k][tx] = W[(size_t)(kt + k) * DMODEL + nt + tx];
        }
        __syncthreads();
#pragma unroll
        for (int i = 0; i < 4; i++) {
            const int n = ty + i * 8;
            Wt[(size_t)(nt + n) * DMODEL + kt + tx] = __float2half_rn(t[tx][n]);
        }
    }
}

// ---------------- tensor-core GEMM body (fp16, 4-stage, frag-pipelined) ------
#define RSTRIDE 80
#define ARR_BYTES (128 * RSTRIDE)
#define STAGE_BYTES (2 * ARR_BYTES)
#define NSTAGE 4
#define GEMM_SMEM (NSTAGE * STAGE_BYTES)   // 81920
#define NCHUNK 16

// Epilogue modes: selected by which output pointers are non-null.
// Cs: scaled fp16; Ch: unscaled fp16; Vt: transposed fp16;
// GeluResid: write Cs = A_row_src + gelu(acc+bias)  (A_row_src = Gr)
__device__ __forceinline__ void gemm_body(
    char* smem, const __half* __restrict__ Af, const __half* __restrict__ Bf,
    const float* __restrict__ bias,
    __half* __restrict__ Cs, float csscale,
    __half* __restrict__ Ch,
    __half* __restrict__ Vt,
    const __half* __restrict__ Gr,   // if non-null: gelu-residual epilogue into Cs
    int bm, int bn)
{
    const uint32_t sbase = smem_u32(smem);
    const int tid = threadIdx.x;
    const int lane = tid & 31, wid = tid >> 5;
    const int wm = wid & 3, wn = wid >> 2;
    const int grp = lane >> 2, tg = lane & 3;

    const int lrow = tid >> 1, lseg = tid & 1;
    const __half* sA = Af + (size_t)(bm + lrow) * DMODEL + lseg * 16;
    const __half* sB = Bf + (size_t)(bn + lrow) * DMODEL + lseg * 16;
    const uint32_t dstoff = lrow * RSTRIDE + lseg * 32;

    const uint32_t a_lm = (uint32_t)(wm * 32 + (lane & 15)) * RSTRIDE + (lane >> 4) * 16;
    const uint32_t b_lm = (uint32_t)(wn * 64 + (lane >> 4) * 8 + (lane & 7)) * RSTRIDE
                        + ((lane >> 3) & 1) * 16;

    float acc[2][8][4];
#pragma unroll
    for (int i = 0; i < 2; i++)
#pragma unroll
        for (int j = 0; j < 8; j++)
#pragma unroll
            for (int r = 0; r < 4; r++) acc[i][j][r] = 0.0f;

#pragma unroll
    for (int s = 0; s < NSTAGE - 1; s++) {
        const int kc = s * 32;
        const uint32_t d = sbase + s * STAGE_BYTES + dstoff;
        cp16(d + 0 * ARR_BYTES, sA + kc); cp16(d + 0 * ARR_BYTES + 16, sA + kc + 8);
        cp16(d + 1 * ARR_BYTES, sB + kc); cp16(d + 1 * ARR_BYTES + 16, sB + kc + 8);
        cp_commit();
    }

#pragma unroll 1
    for (int c = 0; c < NCHUNK; c++) {
        asm volatile("cp.async.wait_group %0;" :: "n"(NSTAGE - 2) : "memory");
        __syncthreads();
        if (c + NSTAGE - 1 < NCHUNK) {
            const int kc = (c + NSTAGE - 1) * 32;
            const uint32_t d = sbase + ((c + NSTAGE - 1) & (NSTAGE - 1)) * STAGE_BYTES + dstoff;
            cp16(d + 0 * ARR_BYTES, sA + kc); cp16(d + 0 * ARR_BYTES + 16, sA + kc + 8);
            cp16(d + 1 * ARR_BYTES, sB + kc); cp16(d + 1 * ARR_BYTES + 16, sB + kc + 8);
        }
        cp_commit();

        const uint32_t st = sbase + (c & (NSTAGE - 1)) * STAGE_BYTES;
        const uint32_t pA = st, pB = st + ARR_BYTES;

        uint32_t afr[2][2][4];
#pragma unroll
        for (int kk = 0; kk < 2; kk++)
#pragma unroll
            for (int mi = 0; mi < 2; mi++)
                ldsm4(afr[kk][mi], pA + a_lm + mi * 16 * RSTRIDE + kk * 32);

        uint32_t bfr[2][4];
        ldsm4(bfr[0], pB + b_lm);
#pragma unroll
        for (int i = 0; i < 8; i++) {
            const int kk = i >> 2, p = i & 3;
            if (i < 7) {
                const int j = i + 1;
                ldsm4(bfr[(i + 1) & 1],
                      pB + b_lm + (j & 3) * 16 * RSTRIDE + (j >> 2) * 32);
            }
            const uint32_t* bf = bfr[i & 1];
#pragma unroll
            for (int mi = 0; mi < 2; mi++) {
                mma16816(acc[mi][2 * p + 0], afr[kk][mi], bf[0], bf[1]);
                mma16816(acc[mi][2 * p + 1], afr[kk][mi], bf[2], bf[3]);
            }
        }
        // NOTE: trailing __syncthreads removed — the top-of-loop barrier
        // (before the next prefetch) already orders consumption vs overwrite.
    }

#pragma unroll
    for (int mi = 0; mi < 2; mi++) {
        const int row = bm + wm * 32 + mi * 16 + grp;
#pragma unroll
        for (int ni = 0; ni < 8; ni++) {
            const int col = bn + wn * 64 + ni * 8 + tg * 2;
            const float2 bv = *(const float2*)&bias[col];
            float2 o0, o1;
            o0.x = acc[mi][ni][0] + bv.x; o0.y = acc[mi][ni][1] + bv.y;
            o1.x = acc[mi][ni][2] + bv.x; o1.y = acc[mi][ni][3] + bv.y;
            if (Gr) {
                const __half2 g0 = *(const __half2*)&Gr[(size_t)row * DMODEL + col];
                const __half2 g1 = *(const __half2*)&Gr[(size_t)(row + 8) * DMODEL + col];
                *(uint32_t*)&Cs[(size_t)row * DMODEL + col] =
                    packh2(__low2float(g0) + gelu_exact(o0.x),
                           __high2float(g0) + gelu_exact(o0.y));
                *(uint32_t*)&Cs[(size_t)(row + 8) * DMODEL + col] =
                    packh2(__low2float(g1) + gelu_exact(o1.x),
                           __high2float(g1) + gelu_exact(o1.y));
            } else if (Cs) {
                *(uint32_t*)&Cs[(size_t)row * DMODEL + col] =
                    packh2(o0.x * csscale, o0.y * csscale);
                *(uint32_t*)&Cs[(size_t)(row + 8) * DMODEL + col] =
                    packh2(o1.x * csscale, o1.y * csscale);
            }
            if (Ch) {
                *(uint32_t*)&Ch[(size_t)row * DMODEL + col] = packh2(o0.x, o0.y);
                *(uint32_t*)&Ch[(size_t)(row + 8) * DMODEL + col] = packh2(o1.x, o1.y);
            }
            if (Vt) {
                const int bb = row >> 10, seq = row & 1023;
                const int hh = col >> 6, d = col & 63;
                const size_t base = ((size_t)((bb * 8 + hh) * 64 + d)) * SEQ + seq;
                Vt[base]           = __float2half_rn(o0.x);
                Vt[base + SEQ]     = __float2half_rn(o0.y);
                Vt[base + 8]       = __float2half_rn(o1.x);
                Vt[base + SEQ + 8] = __float2half_rn(o1.y);
            }
        }
    }
}

__global__ __launch_bounds__(256) void gemm_qkv(
    const __half* __restrict__ Qf, const __half* __restrict__ Kf,
    const __half* __restrict__ Wtq, const __half* __restrict__ Wtk,
    const __half* __restrict__ Wtv,
    const float* __restrict__ bq, const float* __restrict__ bk,
    const float* __restrict__ bv,
    __half* __restrict__ qr,
    __half* __restrict__ qh, __half* __restrict__ kh,
    __half* __restrict__ vt)
{
    extern __shared__ __align__(128) char smem[];
    const int bm = blockIdx.y * 128, bn = blockIdx.x * 128;
    const int z = blockIdx.z;
    if (z == 0)
        gemm_body(smem, Qf, Wtq, bq, qh, QB_SCALE, qr, (__half*)0, (const __half*)0, bm, bn);
    else if (z == 1)
        gemm_body(smem, Kf, Wtk, bk, kh, 1.0f, (__half*)0, (__half*)0, (const __half*)0, bm, bn);
    else
        gemm_body(smem, Kf, Wtv, bv, (__half*)0, 1.0f, (__half*)0, vt, (const __half*)0, bm, bn);
}

// Wo GEMM with fused gelu-residual epilogue: Cs = o1 + gelu(o1@Wo + bo)
__global__ __launch_bounds__(256) void gemm_gelu(
    const __half* __restrict__ Af, const __half* __restrict__ Bf,
    const float* __restrict__ bias, __half* __restrict__ Cs)
{
    extern __shared__ __align__(128) char smem[];
    gemm_body(smem, Af, Bf, bias, Cs, 1.0f, (__half*)0, (__half*)0, Af,
              blockIdx.y * 128, blockIdx.x * 128);
}

// ---------------- tensor-core flash attention (fp16, h2exp2 softmax) ---------
#define NKT (SEQ / 128)
#define KS_STRIDE 144
#define VT_STRIDE 272
#define KS_BYTES (128 * KS_STRIDE)
#define VT_BYTES (64 * VT_STRIDE)
#define ATT_STAGE (KS_BYTES + VT_BYTES)     // 35840
#define ATT_SMEM  (2 * ATT_STAGE)           // 71680

__global__ __launch_bounds__(256, 2) void attn_mma(
    const __half* __restrict__ Qh, const __half* __restrict__ Kh,
    const __half* __restrict__ Vt, __half* __restrict__ O)
{
    extern __shared__ __align__(128) char smem[];
    const uint32_t sbase = smem_u32(smem);
    const int tid = threadIdx.x;
    const int lane = tid & 31, w = tid >> 5;
    const int grp = lane >> 2, tg = lane & 3;
    const int b = blockIdx.z, h = blockIdx.y;
    const int q0 = blockIdx.x * 128;
    const int qrow = q0 + w * 16 + grp;

    uint32_t qa[4][4];
    {
        const uint32_t* q0p = (const uint32_t*)(Qh + (size_t)(b * SEQ + qrow) * DMODEL + h * DHEAD);
        const uint32_t* q8p = (const uint32_t*)(Qh + (size_t)(b * SEQ + qrow + 8) * DMODEL + h * DHEAD);
#pragma unroll
        for (int ks = 0; ks < 4; ks++) {
            qa[ks][0] = q0p[ks * 8 + tg];
            qa[ks][1] = q8p[ks * 8 + tg];
            qa[ks][2] = q0p[ks * 8 + tg + 4];
            qa[ks][3] = q8p[ks * 8 + tg + 4];
        }
    }

    const int kr = tid >> 1, kseg = tid & 1;
    const int vr = tid >> 2, vseg = tid & 3;
    const __half* ksrc = Kh + (size_t)(b * SEQ + kr) * DMODEL + h * DHEAD + kseg * 32;
    const __half* vsrc = Vt + (size_t)((b * NHEAD + h) * DHEAD + vr) * SEQ + vseg * 32;
    const uint32_t kdst = kr * KS_STRIDE + kseg * 64;
    const uint32_t vdst = KS_BYTES + vr * VT_STRIDE + vseg * 64;

    const uint32_t bk_lm = (uint32_t)((lane >> 4) * 8 + (lane & 7)) * KS_STRIDE
                         + ((lane >> 3) & 1) * 16;
    const uint32_t bv_lm = (uint32_t)((lane >> 4) * 8 + (lane & 7)) * VT_STRIDE
                         + ((lane >> 3) & 1) * 16;

    uint32_t oc2[8][2];
#pragma unroll
    for (int i = 0; i < 8; i++) { oc2[i][0] = 0u; oc2[i][1] = 0u; }
    float l0 = 0.0f, l1 = 0.0f;

    {
        const uint32_t s = sbase;
#pragma unroll
        for (int i = 0; i < 4; i++) cp16(s + kdst + i * 16, ksrc + i * 8);
#pragma unroll
        for (int i = 0; i < 4; i++) cp16(s + vdst + i * 16, vsrc + i * 8);
        cp_commit();
    }

#pragma unroll 1
    for (int kt = 0; kt < NKT; kt++) {
        asm volatile("cp.async.wait_group 0;" ::: "memory");
        __syncthreads();
        if (kt + 1 < NKT) {
            const uint32_t s = sbase + ((kt + 1) & 1) * ATT_STAGE;
            const __half* ks2 = ksrc + (size_t)(kt + 1) * 128 * DMODEL;
            const __half* vs2 = vsrc + (kt + 1) * 128;
#pragma unroll
            for (int i = 0; i < 4; i++) cp16(s + kdst + i * 16, ks2 + i * 8);
#pragma unroll
            for (int i = 0; i < 4; i++) cp16(s + vdst + i * 16, vs2 + i * 8);
            cp_commit();
        }

        const uint32_t bufK = sbase + (kt & 1) * ATT_STAGE;
        const uint32_t bufV = bufK + KS_BYTES;

#pragma unroll
        for (int half = 0; half < 2; half++) {
            uint32_t sc2[8][2];
#pragma unroll
            for (int i = 0; i < 8; i++) { sc2[i][0] = 0u; sc2[i][1] = 0u; }

            {
                uint32_t bkf[2][4];
                ldsm4(bkf[0], bufK + bk_lm + (half * 4) * 16 * KS_STRIDE);
#pragma unroll
                for (int i = 0; i < 16; i++) {
                    const int ks = i >> 2, p = i & 3;
                    if (i < 15) {
                        const int j = i + 1;
                        ldsm4(bkf[(i + 1) & 1],
                              bufK + bk_lm + (half * 4 + (j & 3)) * 16 * KS_STRIDE
                              + (j >> 2) * 32);
                    }
                    const uint32_t* bf = bkf[i & 1];
                    mma16816h(sc2[2 * p + 0], qa[ks], bf[0], bf[1]);
                    mma16816h(sc2[2 * p + 1], qa[ks], bf[2], bf[3]);
                }
            }

            uint32_t pf[8][2];
            __half2 lh0 = __half2(__half(0.0f), __half(0.0f));
            __half2 lh1 = lh0;
#pragma unroll
            for (int ni = 0; ni < 8; ni++) {
                const __half2 p01 = h2exp2(*(const __half2*)&sc2[ni][0]);
                const __half2 p23 = h2exp2(*(const __half2*)&sc2[ni][1]);
                pf[ni][0] = *(const uint32_t*)&p01;
                pf[ni][1] = *(const uint32_t*)&p23;
                lh0 = __hadd2(lh0, p01);
                lh1 = __hadd2(lh1, p23);
            }
            l0 += __low2float(lh0) + __high2float(lh0);
            l1 += __low2float(lh1) + __high2float(lh1);

            {
                uint32_t bvf[2][4];
                ldsm4(bvf[0], bufV + bv_lm + half * 128);
#pragma unroll
                for (int i = 0; i < 16; i++) {
                    const int ks = i >> 2, p = i & 3;
                    if (i < 15) {
                        const int j = i + 1;
                        ldsm4(bvf[(i + 1) & 1],
                              bufV + bv_lm + (j & 3) * 16 * VT_STRIDE
                              + (j >> 2) * 32 + half * 128);
                    }
                    uint32_t a[4] = { pf[2 * ks][0], pf[2 * ks][1],
                                      pf[2 * ks + 1][0], pf[2 * ks + 1][1] };
                    const uint32_t* bf = bvf[i & 1];
                    mma16816h(oc2[2 * p + 0], a, bf[0], bf[1]);
                    mma16816h(oc2[2 * p + 1], a, bf[2], bf[3]);
                }
            }
        }
        // trailing __syncthreads removed (top-of-loop barrier covers reuse)
    }

    l0 += __shfl_xor_sync(0xffffffffu, l0, 1);
    l0 += __shfl_xor_sync(0xffffffffu, l0, 2);
    l1 += __shfl_xor_sync(0xffffffffu, l1, 1);
    l1 += __shfl_xor_sync(0xffffffffu, l1, 2);
    const float inv0 = 1.0f / l0, inv1 = 1.0f / l1;
#pragma unroll
    for (int ni = 0; ni < 8; ni++) {
        const int col = h * DHEAD + ni * 8 + tg * 2;
        const __half2 o01 = *(const __half2*)&oc2[ni][0];
        const __half2 o23 = *(const __half2*)&oc2[ni][1];
        *(uint32_t*)&O[(size_t)(b * SEQ + qrow) * DMODEL + col] =
            packh2(__low2float(o01) * inv0, __high2float(o01) * inv0);
        *(uint32_t*)&O[(size_t)(b * SEQ + qrow + 8) * DMODEL + col] =
            packh2(__low2float(o23) * inv1, __high2float(o23) * inv1);
    }
}

// ---------------- warp-per-row LayerNorm kernels ------------------------------
__device__ __forceinline__ float warp_sum(float v) {
#pragma unroll
    for (int off = 16; off >= 1; off >>= 1)
        v += __shfl_xor_sync(0xffffffffu, v, off);
    return v;
}

// af0_out = fp16( LN(qr + att) )
__global__ __launch_bounds__(256) void resid_ln(
    const __half* __restrict__ Qr, const __half* __restrict__ Att,
    uint4* __restrict__ out16)
{
    const int row = blockIdx.x * 8 + (threadIdx.x >> 5);
    const int lane = threadIdx.x & 31;
    const size_t base = (size_t)row * DMODEL + lane * 16;
    const uint4 q0 = *(const uint4*)&Qr[base];
    const uint4 q1 = *(const uint4*)&Qr[base + 8];
    const uint4 a0 = *(const uint4*)&Att[base];
    const uint4 a1 = *(const uint4*)&Att[base + 8];
    uint32_t qr8[8] = {q0.x, q0.y, q0.z, q0.w, q1.x, q1.y, q1.z, q1.w};
    uint32_t at8[8] = {a0.x, a0.y, a0.z, a0.w, a1.x, a1.y, a1.z, a1.w};
    float x[16];
    float s = 0.0f, ss = 0.0f;
#pragma unroll
    for (int i = 0; i < 8; i++) {
        const __half2 qh2 = *(const __half2*)&qr8[i];
        const __half2 ah2 = *(const __half2*)&at8[i];
        const float v0 = __low2float(qh2) + __low2float(ah2);
        const float v1 = __high2float(qh2) + __high2float(ah2);
        x[2 * i] = v0; x[2 * i + 1] = v1;
        s += v0 + v1;
        ss += v0 * v0 + v1 * v1;
    }
    s = warp_sum(s);
    ss = warp_sum(ss);
    const float mean = s * (1.0f / DMODEL);
    const float rstd = rsqrtf(ss * (1.0f / DMODEL) - mean * mean + LN_EPS);
    uint4 o0, o1;
    o0.x = packh2((x[0] - mean) * rstd, (x[1] - mean) * rstd);
    o0.y = packh2((x[2] - mean) * rstd, (x[3] - mean) * rstd);
    o0.z = packh2((x[4] - mean) * rstd, (x[5] - mean) * rstd);
    o0.w = packh2((x[6] - mean) * rstd, (x[7] - mean) * rstd);
    o1.x = packh2((x[8] - mean) * rstd, (x[9] - mean) * rstd);
    o1.y = packh2((x[10] - mean) * rstd, (x[11] - mean) * rstd);
    o1.z = packh2((x[12] - mean) * rstd, (x[13] - mean) * rstd);
    o1.w = packh2((x[14] - mean) * rstd, (x[15] - mean) * rstd);
    out16[base / 8]     = o0;
    out16[base / 8 + 1] = o1;
}

// out_fp32 = LN(x), x fp16 (already o1 + gelu(t))
__global__ __launch_bounds__(256) void final_ln(
    const __half* __restrict__ X, float4* __restrict__ out)
{
    const int row = blockIdx.x * 8 + (threadIdx.x >> 5);
    const int lane = threadIdx.x & 31;
    const size_t base = (size_t)row * DMODEL + lane * 16;
    const uint4 x0 = *(const uint4*)&X[base];
    const uint4 x1 = *(const uint4*)&X[base + 8];
    uint32_t x8[8] = {x0.x, x0.y, x0.z, x0.w, x1.x, x1.y, x1.z, x1.w};
    float x[16];
    float s = 0.0f, ss = 0.0f;
#pragma unroll
    for (int i = 0; i < 8; i++) {
        const __half2 h2 = *(const __half2*)&x8[i];
        const float v0 = __low2float(h2);
        const float v1 = __high2float(h2);
        x[2 * i] = v0; x[2 * i + 1] = v1;
        s += v0 + v1;
        ss += v0 * v0 + v1 * v1;
    }
    s = warp_sum(s);
    ss = warp_sum(ss);
    const float mean = s * (1.0f / DMODEL);
    const float rstd = rsqrtf(ss * (1.0f / DMODEL) - mean * mean + LN_EPS);
#pragma unroll
    for (int i = 0; i < 4; i++) {
        float4 r;
        r.x = (x[4 * i + 0] - mean) * rstd;
        r.y = (x[4 * i + 1] - mean) * rstd;
        r.z = (x[4 * i + 2] - mean) * rstd;
        r.w = (x[4 * i + 3] - mean) * rstd;
        out[base / 4 + i] = r;
    }
}

// ---------------- launch ----------------------------------------------------
extern "C" void kernel_launch(void* const* d_in, const int* in_sizes, int n_in,
                              void* d_out, int out_size)
{
    const float* Q  = (const float*)d_in[0];
    const float* K  = (const float*)d_in[1];
    const float* Wq = (const float*)d_in[2];
    const float* bq = (const float*)d_in[3];
    const float* Wk = (const float*)d_in[4];
    const float* bk = (const float*)d_in[5];
    const float* Wv = (const float*)d_in[6];
    const float* bv = (const float*)d_in[7];
    const float* Wo = (const float*)d_in[8];
    const float* bo = (const float*)d_in[9];
    float* out = (float*)d_out;

    static __half *pqr, *patt, *pt, *paf0, *paf1, *pwtq, *pwtk, *pwtv, *pwto;
    static __half *pqh, *pkh, *pvt;
    static bool init = false;
    if (!init) {
        cudaGetSymbolAddress((void**)&pqr, g_qr);
        cudaGetSymbolAddress((void**)&patt, g_att);
        cudaGetSymbolAddress((void**)&pt, g_t);
        cudaGetSymbolAddress((void**)&paf0, g_af0);
        cudaGetSymbolAddress((void**)&paf1, g_af1);
        cudaGetSymbolAddress((void**)&pwtq, g_wtq);
        cudaGetSymbolAddress((void**)&pwtk, g_wtk);
        cudaGetSymbolAddress((void**)&pwtv, g_wtv);
        cudaGetSymbolAddress((void**)&pwto, g_wto);
        cudaGetSymbolAddress((void**)&pqh, g_qh);
        cudaGetSymbolAddress((void**)&pkh, g_kh);
        cudaGetSymbolAddress((void**)&pvt, g_vt);
        cudaFuncSetAttribute(gemm_qkv, cudaFuncAttributeMaxDynamicSharedMemorySize,
                             GEMM_SMEM);
        cudaFuncSetAttribute(gemm_gelu, cudaFuncAttributeMaxDynamicSharedMemorySize,
                             GEMM_SMEM);
        cudaFuncSetAttribute(attn_mma, cudaFuncAttributeMaxDynamicSharedMemorySize,
                             ATT_SMEM);
        init = true;
    }

    prep_fused<<<PREP_BLOCKS, 256>>>(
        (const float4*)Q, (const float4*)K, (uint2*)paf0, (uint2*)paf1,
        Wq, Wk, Wv, Wo, pwtq, pwtk, pwtv, pwto);

    gemm_qkv<<<dim3(DMODEL / 128, ROWS / 128, 3), 256, GEMM_SMEM>>>(
        paf0, paf1, pwtq, pwtk, pwtv, bq, bk, bv, pqr, pqh, pkh, pvt);

    attn_mma<<<dim3(SEQ / 128, NHEAD, BATCH), 256, ATT_SMEM>>>(pqh, pkh, pvt, patt);

    resid_ln<<<ROWS / 8, 256>>>(pqr, patt, (uint4*)paf0);

    gemm_gelu<<<dim3(DMODEL / 128, ROWS / 128), 256, GEMM_SMEM>>>(paf0, pwto, bo, pt);

    final_ln<<<ROWS / 8, 256>>>(pt, (float4*)out);
}

// round 17
// speedup vs baseline: 1.0146x; 1.0146x over previous
#include <cuda_runtime.h>
#include <cuda_bf16.h>
#include <cuda_fp16.h>
#include <math.h>
#include <stdint.h>

#define BATCH   16
#define SEQ     1024
#define DMODEL  512
#define NHEAD   8
#define DHEAD   64
#define ROWS    (BATCH * SEQ)          // 16384
#define LN_EPS  1e-5f
#define SM_SCALE 0.04419417382415922f  // 1/sqrt(512)
#define QB_SCALE (0.04419417382415922f * 1.4426950408889634f)  // fold log2(e)

// ---------------- scratch (device globals; no allocations allowed) ----------
__device__ __half g_qr[ROWS * DMODEL];          // q projection fp16 (residual)
__device__ __half g_att[ROWS * DMODEL];         // attention output fp16
__device__ __half g_t[ROWS * DMODEL];           // Wo gemm output fp16
__device__ __half g_af0[ROWS * DMODEL];         // Q fp16, later LN(o1) fp16
__device__ __half g_af1[ROWS * DMODEL];         // K fp16
__device__ __half g_wtq[DMODEL * DMODEL];
__device__ __half g_wtk[DMODEL * DMODEL];
__device__ __half g_wtv[DMODEL * DMODEL];
__device__ __half g_wto[DMODEL * DMODEL];
__device__ __half g_qh[ROWS * DMODEL];          // q * QB_SCALE, fp16
__device__ __half g_kh[ROWS * DMODEL];          // k, fp16
__device__ __half g_vt[ROWS * DMODEL];          // v transposed [b][h][d][seq], fp16

// ---------------- helpers ----------------------------------------------------
__device__ __forceinline__ uint32_t smem_u32(const void* p) {
    uint32_t a;
    asm("{ .reg .u64 t; cvta.to.shared.u64 t, %1; cvt.u32.u64 %0, t; }" : "=r"(a) : "l"(p));
    return a;
}
__device__ __forceinline__ void ldsm4(uint32_t* r, uint32_t addr) {
    asm volatile("ldmatrix.sync.aligned.m8n8.x4.shared.b16 {%0,%1,%2,%3}, [%4];"
                 : "=r"(r[0]), "=r"(r[1]), "=r"(r[2]), "=r"(r[3]) : "r"(addr));
}
__device__ __forceinline__ void cp16(uint32_t dst, const void* src) {
    asm volatile("cp.async.cg.shared.global [%0], [%1], 16;" :: "r"(dst), "l"(src) : "memory");
}
__device__ __forceinline__ void cp_commit() {
    asm volatile("cp.async.commit_group;" ::: "memory");
}
__device__ __forceinline__ uint32_t packh2(float a, float b) {
    uint32_t r;
    asm("cvt.rn.f16x2.f32 %0, %1, %2;" : "=r"(r) : "f"(b), "f"(a));
    return r;
}
// fp16 in, fp32 accum (projection GEMMs)
__device__ __forceinline__ void mma16816(float* d, const uint32_t* a, uint32_t b0, uint32_t b1) {
    asm volatile("mma.sync.aligned.m16n8k16.row.col.f32.f16.f16.f32 "
                 "{%0,%1,%2,%3}, {%4,%5,%6,%7}, {%8,%9}, {%0,%1,%2,%3};"
                 : "+f"(d[0]), "+f"(d[1]), "+f"(d[2]), "+f"(d[3])
                 : "r"(a[0]), "r"(a[1]), "r"(a[2]), "r"(a[3]), "r"(b0), "r"(b1));
}
// fp16 in, fp16 accum (attention)
__device__ __forceinline__ void mma16816h(uint32_t* d, const uint32_t* a, uint32_t b0, uint32_t b1) {
    asm volatile("mma.sync.aligned.m16n8k16.row.col.f16.f16.f16.f16 "
                 "{%0,%1}, {%2,%3,%4,%5}, {%6,%7}, {%0,%1};"
                 : "+r"(d[0]), "+r"(d[1])
                 : "r"(a[0]), "r"(a[1]), "r"(a[2]), "r"(a[3]), "r"(b0), "r"(b1));
}
__device__ __forceinline__ float gelu_exact(float x)
{
    return 0.5f * x * (1.0f + erff(x * 0.7071067811865475f));
}

// ---------------- fused prep: converts Q,K rows + 4 weight transposes --------
#define PREP_BLOCKS (2 * 8192 + 4 * 256)

__global__ __launch_bounds__(256) void prep_fused(
    const float4* __restrict__ Q4, const float4* __restrict__ K4,
    uint2* __restrict__ aq, uint2* __restrict__ ak,
    const float* __restrict__ Wq, const float* __restrict__ Wk,
    const float* __restrict__ Wv, const float* __restrict__ Wo,
    __half* __restrict__ wtq, __half* __restrict__ wtk,
    __half* __restrict__ wtv, __half* __restrict__ wto)
{
    const int bid = blockIdx.x;
    const int tid = threadIdx.x;
    if (bid < 16384) {
        const float4* in = (bid < 8192) ? Q4 : K4;
        uint2* out = (bid < 8192) ? aq : ak;
        const size_t i = (size_t)(bid & 8191) * 256 + tid;
        float4 v = in[i];
        uint2 o;
        o.x = packh2(v.x, v.y);
        o.y = packh2(v.z, v.w);
        out[i] = o;
    } else {
        __shared__ float t[32][33];
        const int r = bid - 16384;
        const int w = r >> 8, tile = r & 255;
        const float* W = (w == 0) ? Wq : (w == 1) ? Wk : (w == 2) ? Wv : Wo;
        __half* Wt = (w == 0) ? wtq : (w == 1) ? wtk : (w == 2) ? wtv : wto;
        const int nt = (tile & 15) * 32, kt = (tile >> 4) * 32;
        const int tx = tid & 31, ty = tid >> 5;
#pragma unroll
        for (int i = 0; i < 4; i++) {
            const int k = ty + i * 8;
            t[k][tx] = W[(size_t)(kt + k) * DMODEL + nt + tx];
        }
        __syncthreads();
#pragma unroll
        for (int i = 0; i < 4; i++) {
            const int n = ty + i * 8;
            Wt[(size_t)(nt + n) * DMODEL + kt + tx] = __float2half_rn(t[tx][n]);
        }
    }
}

// ---------------- tensor-core GEMM body (fp16, 4-stage, single barrier) ------
#define RSTRIDE 80
#define ARR_BYTES (128 * RSTRIDE)
#define STAGE_BYTES (2 * ARR_BYTES)
#define NSTAGE 4
#define GEMM_SMEM (NSTAGE * STAGE_BYTES)   // 81920
#define NCHUNK 16

__device__ __forceinline__ void gemm_body(
    char* smem, const __half* __restrict__ Af, const __half* __restrict__ Bf,
    const float* __restrict__ bias,
    __half* __restrict__ Cs, float csscale,   // scaled fp16 out
    __half* __restrict__ Ch,                  // unscaled fp16 out
    __half* __restrict__ Vt, int bm, int bn)  // transposed fp16 out
{
    const uint32_t sbase = smem_u32(smem);
    const int tid = threadIdx.x;
    const int lane = tid & 31, wid = tid >> 5;
    const int wm = wid & 3, wn = wid >> 2;
    const int grp = lane >> 2, tg = lane & 3;

    const int lrow = tid >> 1, lseg = tid & 1;
    const __half* sA = Af + (size_t)(bm + lrow) * DMODEL + lseg * 16;
    const __half* sB = Bf + (size_t)(bn + lrow) * DMODEL + lseg * 16;
    const uint32_t dstoff = lrow * RSTRIDE + lseg * 32;

    const uint32_t a_lm = (uint32_t)(wm * 32 + (lane & 15)) * RSTRIDE + (lane >> 4) * 16;
    const uint32_t b_lm = (uint32_t)(wn * 64 + (lane >> 4) * 8 + (lane & 7)) * RSTRIDE
                        + ((lane >> 3) & 1) * 16;

    float acc[2][8][4];
#pragma unroll
    for (int i = 0; i < 2; i++)
#pragma unroll
        for (int j = 0; j < 8; j++)
#pragma unroll
            for (int r = 0; r < 4; r++) acc[i][j][r] = 0.0f;

#pragma unroll
    for (int s = 0; s < NSTAGE - 1; s++) {
        const int kc = s * 32;
        const uint32_t d = sbase + s * STAGE_BYTES + dstoff;
        cp16(d + 0 * ARR_BYTES, sA + kc); cp16(d + 0 * ARR_BYTES + 16, sA + kc + 8);
        cp16(d + 1 * ARR_BYTES, sB + kc); cp16(d + 1 * ARR_BYTES + 16, sB + kc + 8);
        cp_commit();
    }

#pragma unroll 1
    for (int c = 0; c < NCHUNK; c++) {
        asm volatile("cp.async.wait_group %0;" :: "n"(NSTAGE - 2) : "memory");
        __syncthreads();
        // prefetch AFTER the barrier: sync separates last consumption of the
        // target buffer (iteration c-1) from this overwrite -> single barrier.
        if (c + NSTAGE - 1 < NCHUNK) {
            const int kc = (c + NSTAGE - 1) * 32;
            const uint32_t d = sbase + ((c + NSTAGE - 1) & (NSTAGE - 1)) * STAGE_BYTES + dstoff;
            cp16(d + 0 * ARR_BYTES, sA + kc); cp16(d + 0 * ARR_BYTES + 16, sA + kc + 8);
            cp16(d + 1 * ARR_BYTES, sB + kc); cp16(d + 1 * ARR_BYTES + 16, sB + kc + 8);
        }
        cp_commit();

        const uint32_t st = sbase + (c & (NSTAGE - 1)) * STAGE_BYTES;
        const uint32_t pA = st, pB = st + ARR_BYTES;

        uint32_t afr[2][2][4];
#pragma unroll
        for (int kk = 0; kk < 2; kk++)
#pragma unroll
            for (int mi = 0; mi < 2; mi++)
                ldsm4(afr[kk][mi], pA + a_lm + mi * 16 * RSTRIDE + kk * 32);

        uint32_t bfr[2][4];
        ldsm4(bfr[0], pB + b_lm);
#pragma unroll
        for (int i = 0; i < 8; i++) {
            const int kk = i >> 2, p = i & 3;
            if (i < 7) {
                const int j = i + 1;
                ldsm4(bfr[(i + 1) & 1],
                      pB + b_lm + (j & 3) * 16 * RSTRIDE + (j >> 2) * 32);
            }
            const uint32_t* bf = bfr[i & 1];
#pragma unroll
            for (int mi = 0; mi < 2; mi++) {
                mma16816(acc[mi][2 * p + 0], afr[kk][mi], bf[0], bf[1]);
                mma16816(acc[mi][2 * p + 1], afr[kk][mi], bf[2], bf[3]);
            }
        }
    }

#pragma unroll
    for (int mi = 0; mi < 2; mi++) {
        const int row = bm + wm * 32 + mi * 16 + grp;
#pragma unroll
        for (int ni = 0; ni < 8; ni++) {
            const int col = bn + wn * 64 + ni * 8 + tg * 2;
            const float2 bv = *(const float2*)&bias[col];
            float2 o0, o1;
            o0.x = acc[mi][ni][0] + bv.x; o0.y = acc[mi][ni][1] + bv.y;
            o1.x = acc[mi][ni][2] + bv.x; o1.y = acc[mi][ni][3] + bv.y;
            if (Cs) {
                *(uint32_t*)&Cs[(size_t)row * DMODEL + col] =
                    packh2(o0.x * csscale, o0.y * csscale);
                *(uint32_t*)&Cs[(size_t)(row + 8) * DMODEL + col] =
                    packh2(o1.x * csscale, o1.y * csscale);
            }
            if (Ch) {
                *(uint32_t*)&Ch[(size_t)row * DMODEL + col] = packh2(o0.x, o0.y);
                *(uint32_t*)&Ch[(size_t)(row + 8) * DMODEL + col] = packh2(o1.x, o1.y);
            }
            if (Vt) {
                const int bb = row >> 10, seq = row & 1023;
                const int hh = col >> 6, d = col & 63;
                const size_t base = ((size_t)((bb * 8 + hh) * 64 + d)) * SEQ + seq;
                Vt[base]           = __float2half_rn(o0.x);
                Vt[base + SEQ]     = __float2half_rn(o0.y);
                Vt[base + 8]       = __float2half_rn(o1.x);
                Vt[base + SEQ + 8] = __float2half_rn(o1.y);
            }
        }
    }
}

__global__ __launch_bounds__(256) void gemm_qkv(
    const __half* __restrict__ Qf, const __half* __restrict__ Kf,
    const __half* __restrict__ Wtq, const __half* __restrict__ Wtk,
    const __half* __restrict__ Wtv,
    const float* __restrict__ bq, const float* __restrict__ bk,
    const float* __restrict__ bv,
    __half* __restrict__ qr,
    __half* __restrict__ qh, __half* __restrict__ kh,
    __half* __restrict__ vt)
{
    extern __shared__ __align__(128) char smem[];
    const int bm = blockIdx.y * 128, bn = blockIdx.x * 128;
    const int z = blockIdx.z;
    if (z == 0)
        gemm_body(smem, Qf, Wtq, bq, qh, QB_SCALE, qr, (__half*)0, bm, bn);
    else if (z == 1)
        gemm_body(smem, Kf, Wtk, bk, kh, 1.0f, (__half*)0, (__half*)0, bm, bn);
    else
        gemm_body(smem, Kf, Wtv, bv, (__half*)0, 1.0f, (__half*)0, vt, bm, bn);
}

__global__ __launch_bounds__(256) void gemm_single(
    const __half* __restrict__ Af, const __half* __restrict__ Bf,
    const float* __restrict__ bias, __half* __restrict__ Ch)
{
    extern __shared__ __align__(128) char smem[];
    gemm_body(smem, Af, Bf, bias, (__half*)0, 1.0f, Ch, (__half*)0,
              blockIdx.y * 128, blockIdx.x * 128);
}

// ---------------- tensor-core flash attention (fp16, h2exp2 softmax) ---------
#define NKT (SEQ / 128)
#define KS_STRIDE 144
#define VT_STRIDE 272
#define KS_BYTES (128 * KS_STRIDE)
#define VT_BYTES (64 * VT_STRIDE)
#define ATT_STAGE (KS_BYTES + VT_BYTES)     // 35840
#define ATT_SMEM  (2 * ATT_STAGE)           // 71680

__global__ __launch_bounds__(256, 2) void attn_mma(
    const __half* __restrict__ Qh, const __half* __restrict__ Kh,
    const __half* __restrict__ Vt, __half* __restrict__ O)
{
    extern __shared__ __align__(128) char smem[];
    const uint32_t sbase = smem_u32(smem);
    const int tid = threadIdx.x;
    const int lane = tid & 31, w = tid >> 5;
    const int grp = lane >> 2, tg = lane & 3;
    const int b = blockIdx.z, h = blockIdx.y;
    const int q0 = blockIdx.x * 128;
    const int qrow = q0 + w * 16 + grp;

    uint32_t qa[4][4];
    {
        const uint32_t* q0p = (const uint32_t*)(Qh + (size_t)(b * SEQ + qrow) * DMODEL + h * DHEAD);
        const uint32_t* q8p = (const uint32_t*)(Qh + (size_t)(b * SEQ + qrow + 8) * DMODEL + h * DHEAD);
#pragma unroll
        for (int ks = 0; ks < 4; ks++) {
            qa[ks][0] = q0p[ks * 8 + tg];
            qa[ks][1] = q8p[ks * 8 + tg];
            qa[ks][2] = q0p[ks * 8 + tg + 4];
            qa[ks][3] = q8p[ks * 8 + tg + 4];
        }
    }

    const int kr = tid >> 1, kseg = tid & 1;
    const int vr = tid >> 2, vseg = tid & 3;
    const __half* ksrc = Kh + (size_t)(b * SEQ + kr) * DMODEL + h * DHEAD + kseg * 32;
    const __half* vsrc = Vt + (size_t)((b * NHEAD + h) * DHEAD + vr) * SEQ + vseg * 32;
    const uint32_t kdst = kr * KS_STRIDE + kseg * 64;
    const uint32_t vdst = KS_BYTES + vr * VT_STRIDE + vseg * 64;

    const uint32_t bk_lm = (uint32_t)((lane >> 4) * 8 + (lane & 7)) * KS_STRIDE
                         + ((lane >> 3) & 1) * 16;
    const uint32_t bv_lm = (uint32_t)((lane >> 4) * 8 + (lane & 7)) * VT_STRIDE
                         + ((lane >> 3) & 1) * 16;

    uint32_t oc2[8][2];
#pragma unroll
    for (int i = 0; i < 8; i++) { oc2[i][0] = 0u; oc2[i][1] = 0u; }
    float l0 = 0.0f, l1 = 0.0f;

    {
        const uint32_t s = sbase;
#pragma unroll
        for (int i = 0; i < 4; i++) cp16(s + kdst + i * 16, ksrc + i * 8);
#pragma unroll
        for (int i = 0; i < 4; i++) cp16(s + vdst + i * 16, vsrc + i * 8);
        cp_commit();
    }

#pragma unroll 1
    for (int kt = 0; kt < NKT; kt++) {
        asm volatile("cp.async.wait_group 0;" ::: "memory");
        __syncthreads();
        if (kt + 1 < NKT) {
            const uint32_t s = sbase + ((kt + 1) & 1) * ATT_STAGE;
            const __half* ks2 = ksrc + (size_t)(kt + 1) * 128 * DMODEL;
            const __half* vs2 = vsrc + (kt + 1) * 128;
#pragma unroll
            for (int i = 0; i < 4; i++) cp16(s + kdst + i * 16, ks2 + i * 8);
#pragma unroll
            for (int i = 0; i < 4; i++) cp16(s + vdst + i * 16, vs2 + i * 8);
            cp_commit();
        }

        const uint32_t bufK = sbase + (kt & 1) * ATT_STAGE;
        const uint32_t bufV = bufK + KS_BYTES;

#pragma unroll
        for (int half = 0; half < 2; half++) {
            uint32_t sc2[8][2];
#pragma unroll
            for (int i = 0; i < 8; i++) { sc2[i][0] = 0u; sc2[i][1] = 0u; }

            {
                uint32_t bkf[2][4];
                ldsm4(bkf[0], bufK + bk_lm + (half * 4) * 16 * KS_STRIDE);
#pragma unroll
                for (int i = 0; i < 16; i++) {
                    const int ks = i >> 2, p = i & 3;
                    if (i < 15) {
                        const int j = i + 1;
                        ldsm4(bkf[(i + 1) & 1],
                              bufK + bk_lm + (half * 4 + (j & 3)) * 16 * KS_STRIDE
                              + (j >> 2) * 32);
                    }
                    const uint32_t* bf = bkf[i & 1];
                    mma16816h(sc2[2 * p + 0], qa[ks], bf[0], bf[1]);
                    mma16816h(sc2[2 * p + 1], qa[ks], bf[2], bf[3]);
                }
            }

            uint32_t pf[8][2];
            __half2 lh0 = __half2(__half(0.0f), __half(0.0f));
            __half2 lh1 = lh0;
#pragma unroll
            for (int ni = 0; ni < 8; ni++) {
                const __half2 p01 = h2exp2(*(const __half2*)&sc2[ni][0]);
                const __half2 p23 = h2exp2(*(const __half2*)&sc2[ni][1]);
                pf[ni][0] = *(const uint32_t*)&p01;
                pf[ni][1] = *(const uint32_t*)&p23;
                lh0 = __hadd2(lh0, p01);
                lh1 = __hadd2(lh1, p23);
            }
            l0 += __low2float(lh0) + __high2float(lh0);
            l1 += __low2float(lh1) + __high2float(lh1);

            {
                uint32_t bvf[2][4];
                ldsm4(bvf[0], bufV + bv_lm + half * 128);
#pragma unroll
                for (int i = 0; i < 16; i++) {
                    const int ks = i >> 2, p = i & 3;
                    if (i < 15) {
                        const int j = i + 1;
                        ldsm4(bvf[(i + 1) & 1],
                              bufV + bv_lm + (j & 3) * 16 * VT_STRIDE
                              + (j >> 2) * 32 + half * 128);
                    }
                    uint32_t a[4] = { pf[2 * ks][0], pf[2 * ks][1],
                                      pf[2 * ks + 1][0], pf[2 * ks + 1][1] };
                    const uint32_t* bf = bvf[i & 1];
                    mma16816h(oc2[2 * p + 0], a, bf[0], bf[1]);
                    mma16816h(oc2[2 * p + 1], a, bf[2], bf[3]);
                }
            }
        }
    }

    l0 += __shfl_xor_sync(0xffffffffu, l0, 1);
    l0 += __shfl_xor_sync(0xffffffffu, l0, 2);
    l1 += __shfl_xor_sync(0xffffffffu, l1, 1);
    l1 += __shfl_xor_sync(0xffffffffu, l1, 2);
    const float inv0 = 1.0f / l0, inv1 = 1.0f / l1;
#pragma unroll
    for (int ni = 0; ni < 8; ni++) {
        const int col = h * DHEAD + ni * 8 + tg * 2;
        const __half2 o01 = *(const __half2*)&oc2[ni][0];
        const __half2 o23 = *(const __half2*)&oc2[ni][1];
        *(uint32_t*)&O[(size_t)(b * SEQ + qrow) * DMODEL + col] =
            packh2(__low2float(o01) * inv0, __high2float(o01) * inv0);
        *(uint32_t*)&O[(size_t)(b * SEQ + qrow + 8) * DMODEL + col] =
            packh2(__low2float(o23) * inv1, __high2float(o23) * inv1);
    }
}

// ---------------- warp-per-row LayerNorm kernels ------------------------------
__device__ __forceinline__ float warp_sum(float v) {
#pragma unroll
    for (int off = 16; off >= 1; off >>= 1)
        v += __shfl_xor_sync(0xffffffffu, v, off);
    return v;
}

// af0_out = fp16( LN(qr + att) )
__global__ __launch_bounds__(256) void resid_ln(
    const __half* __restrict__ Qr, const __half* __restrict__ Att,
    uint4* __restrict__ out16)
{
    const int row = blockIdx.x * 8 + (threadIdx.x >> 5);
    const int lane = threadIdx.x & 31;
    const size_t base = (size_t)row * DMODEL + lane * 16;
    const uint4 q0 = *(const uint4*)&Qr[base];
    const uint4 q1 = *(const uint4*)&Qr[base + 8];
    const uint4 a0 = *(const uint4*)&Att[base];
    const uint4 a1 = *(const uint4*)&Att[base + 8];
    uint32_t qr8[8] = {q0.x, q0.y, q0.z, q0.w, q1.x, q1.y, q1.z, q1.w};
    uint32_t at8[8] = {a0.x, a0.y, a0.z, a0.w, a1.x, a1.y, a1.z, a1.w};
    float x[16];
    float s = 0.0f, ss = 0.0f;
#pragma unroll
    for (int i = 0; i < 8; i++) {
        const __half2 qh2 = *(const __half2*)&qr8[i];
        const __half2 ah2 = *(const __half2*)&at8[i];
        const float v0 = __low2float(qh2) + __low2float(ah2);
        const float v1 = __high2float(qh2) + __high2float(ah2);
        x[2 * i] = v0; x[2 * i + 1] = v1;
        s += v0 + v1;
        ss += v0 * v0 + v1 * v1;
    }
    s = warp_sum(s);
    ss = warp_sum(ss);
    const float mean = s * (1.0f / DMODEL);
    const float rstd = rsqrtf(ss * (1.0f / DMODEL) - mean * mean + LN_EPS);
    uint4 o0, o1;
    o0.x = packh2((x[0] - mean) * rstd, (x[1] - mean) * rstd);
    o0.y = packh2((x[2] - mean) * rstd, (x[3] - mean) * rstd);
    o0.z = packh2((x[4] - mean) * rstd, (x[5] - mean) * rstd);
    o0.w = packh2((x[6] - mean) * rstd, (x[7] - mean) * rstd);
    o1.x = packh2((x[8] - mean) * rstd, (x[9] - mean) * rstd);
    o1.y = packh2((x[10] - mean) * rstd, (x[11] - mean) * rstd);
    o1.z = packh2((x[12] - mean) * rstd, (x[13] - mean) * rstd);
    o1.w = packh2((x[14] - mean) * rstd, (x[15] - mean) * rstd);
    out16[base / 8]     = o0;
    out16[base / 8 + 1] = o1;
}

// out = LN( o1 + gelu(t) ), o1 and t fp16, out fp32
__global__ __launch_bounds__(256) void gelu_resid_ln(
    const __half* __restrict__ O1, const __half* __restrict__ T,
    float4* __restrict__ out)
{
    const int row = blockIdx.x * 8 + (threadIdx.x >> 5);
    const int lane = threadIdx.x & 31;
    const size_t base = (size_t)row * DMODEL + lane * 16;
    const uint4 q0 = *(const uint4*)&O1[base];
    const uint4 q1 = *(const uint4*)&O1[base + 8];
    const uint4 a0 = *(const uint4*)&T[base];
    const uint4 a1 = *(const uint4*)&T[base + 8];
    uint32_t o8[8] = {q0.x, q0.y, q0.z, q0.w, q1.x, q1.y, q1.z, q1.w};
    uint32_t t8[8] = {a0.x, a0.y, a0.z, a0.w, a1.x, a1.y, a1.z, a1.w};
    float x[16];
    float s = 0.0f, ss = 0.0f;
#pragma unroll
    for (int i = 0; i < 8; i++) {
        const __half2 oh2 = *(const __half2*)&o8[i];
        const __half2 th2 = *(const __half2*)&t8[i];
        const float v0 = __low2float(oh2)  + gelu_exact(__low2float(th2));
        const float v1 = __high2float(oh2) + gelu_exact(__high2float(th2));
        x[2 * i] = v0; x[2 * i + 1] = v1;
        s += v0 + v1;
        ss += v0 * v0 + v1 * v1;
    }
    s = warp_sum(s);
    ss = warp_sum(ss);
    const float mean = s * (1.0f / DMODEL);
    const float rstd = rsqrtf(ss * (1.0f / DMODEL) - mean * mean + LN_EPS);
#pragma unroll
    for (int i = 0; i < 4; i++) {
        float4 r;
        r.x = (x[4 * i + 0] - mean) * rstd;
        r.y = (x[4 * i + 1] - mean) * rstd;
        r.z = (x[4 * i + 2] - mean) * rstd;
        r.w = (x[4 * i + 3] - mean) * rstd;
        out[base / 4 + i] = r;
    }
}

// ---------------- launch ----------------------------------------------------
extern "C" void kernel_launch(void* const* d_in, const int* in_sizes, int n_in,
                              void* d_out, int out_size)
{
    const float* Q  = (const float*)d_in[0];
    const float* K  = (const float*)d_in[1];
    const float* Wq = (const float*)d_in[2];
    const float* bq = (const float*)d_in[3];
    const float* Wk = (const float*)d_in[4];
    const float* bk = (const float*)d_in[5];
    const float* Wv = (const float*)d_in[6];
    const float* bv = (const float*)d_in[7];
    const float* Wo = (const float*)d_in[8];
    const float* bo = (const float*)d_in[9];
    float* out = (float*)d_out;

    static __half *pqr, *patt, *pt, *paf0, *paf1, *pwtq, *pwtk, *pwtv, *pwto;
    static __half *pqh, *pkh, *pvt;
    static bool init = false;
    if (!init) {
        cudaGetSymbolAddress((void**)&pqr, g_qr);
        cudaGetSymbolAddress((void**)&patt, g_att);
        cudaGetSymbolAddress((void**)&pt, g_t);
        cudaGetSymbolAddress((void**)&paf0, g_af0);
        cudaGetSymbolAddress((void**)&paf1, g_af1);
        cudaGetSymbolAddress((void**)&pwtq, g_wtq);
        cudaGetSymbolAddress((void**)&pwtk, g_wtk);
        cudaGetSymbolAddress((void**)&pwtv, g_wtv);
        cudaGetSymbolAddress((void**)&pwto, g_wto);
        cudaGetSymbolAddress((void**)&pqh, g_qh);
        cudaGetSymbolAddress((void**)&pkh, g_kh);
        cudaGetSymbolAddress((void**)&pvt, g_vt);
        cudaFuncSetAttribute(gemm_qkv, cudaFuncAttributeMaxDynamicSharedMemorySize,
                             GEMM_SMEM);
        cudaFuncSetAttribute(gemm_single, cudaFuncAttributeMaxDynamicSharedMemorySize,
                             GEMM_SMEM);
        cudaFuncSetAttribute(attn_mma, cudaFuncAttributeMaxDynamicSharedMemorySize,
                             ATT_SMEM);
        init = true;
    }

    prep_fused<<<PREP_BLOCKS, 256>>>(
        (const float4*)Q, (const float4*)K, (uint2*)paf0, (uint2*)paf1,
        Wq, Wk, Wv, Wo, pwtq, pwtk, pwtv, pwto);

    gemm_qkv<<<dim3(DMODEL / 128, ROWS / 128, 3), 256, GEMM_SMEM>>>(
        paf0, paf1, pwtq, pwtk, pwtv, bq, bk, bv, pqr, pqh, pkh, pvt);

    attn_mma<<<dim3(SEQ / 128, NHEAD, BATCH), 256, ATT_SMEM>>>(pqh, pkh, pvt, patt);

    resid_ln<<<ROWS / 8, 256>>>(pqr, patt, (uint4*)paf0);

    gemm_single<<<dim3(DMODEL / 128, ROWS / 128), 256, GEMM_SMEM>>>(paf0, pwto, bo, pt);

    gelu_resid_ln<<<ROWS / 8, 256>>>(paf0, pt, (float4*)out);
}